// round 1
// baseline (speedup 1.0000x reference)
#include <cuda_runtime.h>
#include <cstdint>
#include <cstddef>

// Problem constants
#define BB   8
#define TT   1024
#define DD   512
#define EE   1024      // 2*D projection width
#define NTAPE 64
#define CPB  16        // CTAs per batch
#define RPC  32        // rows (and tape cols) per CTA = D / CPB
#define NTHREADS 256

// ---------------- device scratch (static: no allocations allowed) ----------
__device__ float    g_xz[(size_t)BB * TT * EE];     // projected x || z  (33.5 MB)
__device__ float    g_rs[BB * CPB * NTAPE];         // read-score partials
__device__ float    g_ws[BB * CPB * NTAPE];         // write-score partials
__device__ float    g_hnew[BB * DD];                // h_new exchange
__device__ unsigned g_bar[BB];                      // per-batch barrier counters

__global__ void init_bar_kernel() {
    if (threadIdx.x < BB) g_bar[threadIdx.x] = 0u;
}

// ---------------- projection GEMM: g_xz[m][e] = sum_k X[m][k]*Wxz[e][k] ----
// M = B*T = 8192, E = 1024, K = 512.  64x64 tile, 256 threads, 4x4 micro.
__global__ __launch_bounds__(256) void gemm_xz_kernel(
    const float* __restrict__ X, const float* __restrict__ W)
{
    __shared__ float As[16][68];
    __shared__ float Bs[16][68];

    const int m0 = blockIdx.y * 64;
    const int e0 = blockIdx.x * 64;
    const int tid = threadIdx.x;
    const int tx = tid & 15;        // e micro-tile
    const int ty = tid >> 4;        // m micro-tile
    const int lr = tid >> 2;        // 0..63 load row
    const int lc = (tid & 3) * 4;   // 0,4,8,12 load col (k)

    float acc[4][4] = {};

    for (int kt = 0; kt < 512; kt += 16) {
        float4 xv = *(const float4*)(X + (size_t)(m0 + lr) * 512 + kt + lc);
        float4 wv = *(const float4*)(W + (size_t)(e0 + lr) * 512 + kt + lc);
        __syncthreads();
        As[lc + 0][lr] = xv.x; As[lc + 1][lr] = xv.y;
        As[lc + 2][lr] = xv.z; As[lc + 3][lr] = xv.w;
        Bs[lc + 0][lr] = wv.x; Bs[lc + 1][lr] = wv.y;
        Bs[lc + 2][lr] = wv.z; Bs[lc + 3][lr] = wv.w;
        __syncthreads();
#pragma unroll
        for (int kk = 0; kk < 16; kk++) {
            float4 a  = *(const float4*)&As[kk][ty * 4];
            float4 bv = *(const float4*)&Bs[kk][tx * 4];
            float av[4] = {a.x, a.y, a.z, a.w};
            float bw[4] = {bv.x, bv.y, bv.z, bv.w};
#pragma unroll
            for (int i = 0; i < 4; i++)
#pragma unroll
                for (int j = 0; j < 4; j++)
                    acc[i][j] += av[i] * bw[j];
        }
    }
#pragma unroll
    for (int i = 0; i < 4; i++) {
        float4 o = make_float4(acc[i][0], acc[i][1], acc[i][2], acc[i][3]);
        *(float4*)(&g_xz[(size_t)(m0 + ty * 4 + i) * EE + e0 + tx * 4]) = o;
    }
}

// ---------------- scan kernel --------------------------------------------
struct ScanSmem {
    float Wh[RPC * 512];      // 64 KB
    float Ww[RPC * 512];      // 64 KB
    float tape[NTAPE * 33];   // padded rows (bank-conflict free)
    float hwork[512];
    float hnew[512];
    float acc[RPC];
    float wv[RPC];
    float rv[RPC];
    float attn[NTAPE];
    float score[NTAPE];
    float bh[RPC], gz[RPC], gr[RPC], gh[RPC], bg[RPC];
};

__device__ __forceinline__ unsigned ld_acq_u32(const unsigned* p) {
    unsigned v;
    asm volatile("ld.global.acquire.gpu.u32 %0, [%1];" : "=r"(v) : "l"(p));
    return v;
}

// Per-batch barrier across CPB CTAs. Monotonic counter, reset per launch.
__device__ __forceinline__ void batch_barrier(int b, unsigned target) {
    __syncthreads();
    if (threadIdx.x == 0) {
        __threadfence();
        atomicAdd(&g_bar[b], 1u);
        while (ld_acq_u32(&g_bar[b]) < target) { /* spin on L2 */ }
    }
    __syncthreads();
}

// dest[r] = sum_j sW[r*512+j] * vec[j], r = 0..31.  8 warps, 4 rows each.
__device__ __forceinline__ void matvec32(const float* __restrict__ sW,
                                         const float* __restrict__ vec,
                                         float* __restrict__ dest)
{
    const int lane = threadIdx.x & 31;
    const int warp = threadIdx.x >> 5;
    const float4* v = (const float4*)(vec + lane * 16);
    float4 v0 = v[0], v1 = v[1], v2 = v[2], v3 = v[3];
#pragma unroll
    for (int rr = 0; rr < 4; rr++) {
        int r = warp * 4 + rr;
        const float4* w = (const float4*)(sW + r * 512 + lane * 16);
        float4 w0 = w[0], w1 = w[1], w2 = w[2], w3 = w[3];
        float s = w0.x * v0.x + w0.y * v0.y + w0.z * v0.z + w0.w * v0.w
                + w1.x * v1.x + w1.y * v1.y + w1.z * v1.z + w1.w * v1.w
                + w2.x * v2.x + w2.y * v2.y + w2.z * v2.z + w2.w * v2.w
                + w3.x * v3.x + w3.y * v3.y + w3.z * v3.z + w3.w * v3.w;
#pragma unroll
        for (int off = 16; off >= 1; off >>= 1)
            s += __shfl_down_sync(0xffffffffu, s, off);
        if (lane == 0) dest[r] = s;
    }
}

// softmax over 64 values in S.score -> S.attn, computed by warp 0.
__device__ __forceinline__ void softmax64(ScanSmem& S) {
    int t = threadIdx.x;
    if (t < 32) {
        float a = S.score[t], b = S.score[t + 32];
        float m = fmaxf(a, b);
#pragma unroll
        for (int off = 16; off >= 1; off >>= 1)
            m = fmaxf(m, __shfl_xor_sync(0xffffffffu, m, off));
        float e0 = __expf(a - m), e1 = __expf(b - m);
        float ss = e0 + e1;
#pragma unroll
        for (int off = 16; off >= 1; off >>= 1)
            ss += __shfl_xor_sync(0xffffffffu, ss, off);
        float inv = 1.f / ss;
        S.attn[t] = e0 * inv;
        S.attn[t + 32] = e1 * inv;
    }
}

__global__ __launch_bounds__(NTHREADS, 1) void scan_kernel(
    const float* __restrict__ tape_init,
    const float* __restrict__ hwork_init,
    const float* __restrict__ W_h,
    const float* __restrict__ b_h,
    const float* __restrict__ W_write,
    const float* __restrict__ gzv,
    const float* __restrict__ grv,
    const float* __restrict__ ghv,
    const float* __restrict__ bgv,
    float* __restrict__ out)
{
    extern __shared__ char raw[];
    ScanSmem& S = *(ScanSmem*)raw;

    const int t  = threadIdx.x;
    const int b  = blockIdx.x / CPB;
    const int c  = blockIdx.x % CPB;
    const int d0 = c * RPC;
    const float scale = 0.044194173824159216f;  // 1/sqrt(512)

    // ---- one-time loads: weights shard, tape shard, h_work, params ----
    for (int i = t; i < RPC * 512; i += NTHREADS) {
        S.Wh[i] = W_h[(size_t)d0 * 512 + i];
        S.Ww[i] = W_write[(size_t)d0 * 512 + i];
    }
    for (int i = t; i < NTAPE * RPC; i += NTHREADS) {
        int n = i >> 5, dl = i & 31;
        S.tape[n * 33 + dl] = tape_init[(size_t)(b * NTAPE + n) * DD + d0 + dl];
    }
    for (int i = t; i < 512; i += NTHREADS)
        S.hwork[i] = hwork_init[b * 512 + i];
    if (t < RPC) {
        S.bh[t] = b_h[d0 + t];  S.gz[t] = gzv[d0 + t];
        S.gr[t] = grv[d0 + t];  S.gh[t] = ghv[d0 + t];
        S.bg[t] = bgv[d0 + t];
    }
    __syncthreads();

    unsigned bc = 0;
    const int n4 = t >> 2, q4 = t & 3;   // read/write-score partials layout
    const int dl8 = t >> 3, q8 = t & 7;  // read_val layout

    for (int step = 0; step < TT; step++) {
        // ---- Phase A: read-score partials + W_h matvec ----
        {
            float s = 0.f;
#pragma unroll
            for (int k = 0; k < 8; k++) {
                int dl = q4 * 8 + k;
                s += S.hwork[d0 + dl] * S.tape[n4 * 33 + dl];
            }
            s += __shfl_down_sync(0xffffffffu, s, 2);
            s += __shfl_down_sync(0xffffffffu, s, 1);
            if (q4 == 0) g_rs[(b * CPB + c) * NTAPE + n4] = s;
        }
        matvec32(S.Wh, S.hwork, S.acc);
        batch_barrier(b, (++bc) * CPB);

        // ---- Phase B: softmax(read), read_val, h_new, output ----
        if (t < NTAPE) {
            float s = 0.f;
#pragma unroll
            for (int cc = 0; cc < CPB; cc++)
                s += __ldcg(&g_rs[(b * CPB + cc) * NTAPE + t]);
            S.score[t] = s * scale;
        }
        __syncthreads();
        softmax64(S);
        __syncthreads();
        {
            float s = 0.f;
#pragma unroll
            for (int k = 0; k < 8; k++) {
                int n = q8 * 8 + k;
                s += S.attn[n] * S.tape[n * 33 + dl8];
            }
            s += __shfl_down_sync(0xffffffffu, s, 4);
            s += __shfl_down_sync(0xffffffffu, s, 2);
            s += __shfl_down_sync(0xffffffffu, s, 1);
            if (q8 == 0) S.rv[dl8] = s;
        }
        __syncthreads();
        if (t < RPC) {
            size_t row = (size_t)(b * TT + step) * EE;
            float xp = g_xz[row + d0 + t];
            float zt = g_xz[row + 512 + d0 + t];
            float hn = tanhf(xp + S.acc[t] + S.rv[t] + S.bh[t]);
            g_hnew[b * 512 + d0 + t] = hn;
            float gi = zt * S.gz[t] + S.rv[t] * S.gr[t] + hn * S.gh[t] + S.bg[t];
            gi = fminf(fmaxf(gi, -20.f), 20.f);
            float sig = 1.f / (1.f + __expf(-gi));
            out[(size_t)(b * TT + step) * DD + d0 + t] = hn * gi * sig;
        }
        batch_barrier(b, (++bc) * CPB);

        // ---- Phase C: gather h_new, W_write matvec, write-score partials ----
        S.hnew[t]       = __ldcg(&g_hnew[b * 512 + t]);
        S.hnew[t + 256] = __ldcg(&g_hnew[b * 512 + t + 256]);
        __syncthreads();
        matvec32(S.Ww, S.hnew, S.wv);
        __syncthreads();
        {
            float s = 0.f;
#pragma unroll
            for (int k = 0; k < 8; k++) {
                int dl = q4 * 8 + k;
                s += S.wv[dl] * S.tape[n4 * 33 + dl];
            }
            s += __shfl_down_sync(0xffffffffu, s, 2);
            s += __shfl_down_sync(0xffffffffu, s, 1);
            if (q4 == 0) g_ws[(b * CPB + c) * NTAPE + n4] = s;
        }
        batch_barrier(b, (++bc) * CPB);

        // ---- Phase D: softmax(write), tape update, h_work <- h_new ----
        if (t < NTAPE) {
            float s = 0.f;
#pragma unroll
            for (int cc = 0; cc < CPB; cc++)
                s += __ldcg(&g_ws[(b * CPB + cc) * NTAPE + t]);
            S.score[t] = s * scale;
        }
        __syncthreads();
        softmax64(S);
        __syncthreads();
        for (int e = t; e < NTAPE * RPC; e += NTHREADS) {
            int n = e >> 5, dl = e & 31;
            float a  = S.attn[n];
            float tp = S.tape[n * 33 + dl];
            S.tape[n * 33 + dl] = tp - tp * a + S.wv[dl] * a;
        }
        S.hwork[t]       = S.hnew[t];
        S.hwork[t + 256] = S.hnew[t + 256];
        __syncthreads();
    }

    // ---- final tape output ----
    for (int e = t; e < NTAPE * RPC; e += NTHREADS) {
        int n = e >> 5, dl = e & 31;
        out[(size_t)BB * TT * DD + (size_t)(b * NTAPE + n) * DD + d0 + dl] =
            S.tape[n * 33 + dl];
    }
}

// ---------------- launch ---------------------------------------------------
extern "C" void kernel_launch(void* const* d_in, const int* in_sizes, int n_in,
                              void* d_out, int out_size)
{
    const float* x         = (const float*)d_in[0];
    const float* tape_init = (const float*)d_in[1];
    const float* hwork     = (const float*)d_in[2];
    const float* W_h       = (const float*)d_in[3];
    const float* W_xz      = (const float*)d_in[4];
    const float* b_h       = (const float*)d_in[5];
    const float* W_write   = (const float*)d_in[6];
    const float* g_z       = (const float*)d_in[7];
    const float* g_r       = (const float*)d_in[8];
    const float* g_h       = (const float*)d_in[9];
    const float* b_gate    = (const float*)d_in[10];
    float* out = (float*)d_out;

    static_assert(sizeof(ScanSmem) < 220 * 1024, "smem too big");
    cudaFuncSetAttribute((const void*)scan_kernel,
                         cudaFuncAttributeMaxDynamicSharedMemorySize,
                         (int)sizeof(ScanSmem));

    init_bar_kernel<<<1, 32>>>();
    gemm_xz_kernel<<<dim3(EE / 64, (BB * TT) / 64), 256>>>(x, W_xz);
    scan_kernel<<<BB * CPB, NTHREADS, sizeof(ScanSmem)>>>(
        tape_init, hwork, W_h, b_h, W_write, g_z, g_r, g_h, b_gate, out);
}